// round 1
// baseline (speedup 1.0000x reference)
#include <cuda_runtime.h>
#include <cuda_bf16.h>

// Problem constants
#define BATCH 32
#define CH    256
#define NPIX  3136          // 56*56

// Intermediates as device globals (no allocation allowed in kernel_launch).
__device__ float g_q[(size_t)BATCH * CH * NPIX];   // conv1 output  (~103 MB)
__device__ float g_s[(size_t)BATCH * CH * CH];     // scores / attn (~8.4 MB)
__device__ float g_o[(size_t)BATCH * CH * NPIX];   // attn @ q      (~103 MB)

// ---------------------------------------------------------------------------
// NN GEMM: C[b] = A[b](MxK, row-major) * B[b](KxN, row-major) (+ bias[m])
// BM=64, BN=64, BK=16, 256 threads, 4x4 per thread.
// Requires M%64==0, N%64==0, K%16==0, N%4==0, K%4==0.
// ---------------------------------------------------------------------------
__global__ void gemm_nn(const float* __restrict__ A, size_t sA,
                        const float* __restrict__ B, size_t sB,
                        float* __restrict__ C, size_t sC,
                        const float* __restrict__ bias,
                        int M, int N, int K)
{
    constexpr int BM = 64, BN = 64, BK = 16;
    __shared__ float As[BK][BM];     // transposed A tile
    __shared__ float Bs[BK][BN];

    const int bz = blockIdx.z;
    A += (size_t)bz * sA;
    B += (size_t)bz * sB;
    C += (size_t)bz * sC;

    const int m0 = blockIdx.y * BM;
    const int n0 = blockIdx.x * BN;
    const int tid = threadIdx.x;
    const int trow = tid >> 4;        // 0..15
    const int tcol = tid & 15;        // 0..15

    // A-tile load mapping: 64 rows x 16 cols, one float4 per thread
    const int arow = tid >> 2;            // 0..63
    const int acg  = (tid & 3) * 4;       // 0,4,8,12
    // B-tile load mapping: 16 rows x 64 cols, one float4 per thread
    const int brow = tid >> 4;            // 0..15
    const int bcg  = (tid & 15) * 4;      // 0..60

    float acc[4][4] = {};

    for (int k0 = 0; k0 < K; k0 += BK) {
        float4 av = *(const float4*)&A[(size_t)(m0 + arow) * K + k0 + acg];
        As[acg + 0][arow] = av.x;
        As[acg + 1][arow] = av.y;
        As[acg + 2][arow] = av.z;
        As[acg + 3][arow] = av.w;
        float4 bv = *(const float4*)&B[(size_t)(k0 + brow) * N + n0 + bcg];
        *(float4*)&Bs[brow][bcg] = bv;
        __syncthreads();

        #pragma unroll
        for (int k = 0; k < BK; k++) {
            float4 ra = *(const float4*)&As[k][trow * 4];
            float4 rb = *(const float4*)&Bs[k][tcol * 4];
            float a[4] = {ra.x, ra.y, ra.z, ra.w};
            float b[4] = {rb.x, rb.y, rb.z, rb.w};
            #pragma unroll
            for (int i = 0; i < 4; i++)
                #pragma unroll
                for (int j = 0; j < 4; j++)
                    acc[i][j] += a[i] * b[j];
        }
        __syncthreads();
    }

    #pragma unroll
    for (int i = 0; i < 4; i++) {
        const int m = m0 + trow * 4 + i;
        const float bb = bias ? bias[m] : 0.0f;
        float4 v;
        v.x = acc[i][0] + bb;
        v.y = acc[i][1] + bb;
        v.z = acc[i][2] + bb;
        v.w = acc[i][3] + bb;
        *(float4*)&C[(size_t)m * N + n0 + tcol * 4] = v;
    }
}

// ---------------------------------------------------------------------------
// NT GEMM (Gram): C[b](MxN) = A[b](MxK) * B[b](NxK)^T  — K is contiguous dim.
// Same tiling; both tiles loaded like the NN A-tile.
// ---------------------------------------------------------------------------
__global__ void gemm_nt(const float* __restrict__ A, size_t sA,
                        const float* __restrict__ B, size_t sB,
                        float* __restrict__ C, size_t sC,
                        int M, int N, int K)
{
    constexpr int BM = 64, BN = 64, BK = 16;
    __shared__ float As[BK][BM];
    __shared__ float Bs[BK][BN];

    const int bz = blockIdx.z;
    A += (size_t)bz * sA;
    B += (size_t)bz * sB;
    C += (size_t)bz * sC;

    const int m0 = blockIdx.y * BM;
    const int n0 = blockIdx.x * BN;
    const int tid = threadIdx.x;
    const int trow = tid >> 4;
    const int tcol = tid & 15;

    const int lrow = tid >> 2;            // 0..63
    const int lcg  = (tid & 3) * 4;       // 0,4,8,12

    float acc[4][4] = {};

    for (int k0 = 0; k0 < K; k0 += BK) {
        float4 av = *(const float4*)&A[(size_t)(m0 + lrow) * K + k0 + lcg];
        As[lcg + 0][lrow] = av.x;
        As[lcg + 1][lrow] = av.y;
        As[lcg + 2][lrow] = av.z;
        As[lcg + 3][lrow] = av.w;
        float4 bv = *(const float4*)&B[(size_t)(n0 + lrow) * K + k0 + lcg];
        Bs[lcg + 0][lrow] = bv.x;
        Bs[lcg + 1][lrow] = bv.y;
        Bs[lcg + 2][lrow] = bv.z;
        Bs[lcg + 3][lrow] = bv.w;
        __syncthreads();

        #pragma unroll
        for (int k = 0; k < BK; k++) {
            float4 ra = *(const float4*)&As[k][trow * 4];
            float4 rb = *(const float4*)&Bs[k][tcol * 4];
            float a[4] = {ra.x, ra.y, ra.z, ra.w};
            float b[4] = {rb.x, rb.y, rb.z, rb.w};
            #pragma unroll
            for (int i = 0; i < 4; i++)
                #pragma unroll
                for (int j = 0; j < 4; j++)
                    acc[i][j] += a[i] * b[j];
        }
        __syncthreads();
    }

    #pragma unroll
    for (int i = 0; i < 4; i++) {
        const int m = m0 + trow * 4 + i;
        float4 v;
        v.x = acc[i][0];
        v.y = acc[i][1];
        v.z = acc[i][2];
        v.w = acc[i][3];
        *(float4*)&C[(size_t)m * N + n0 + tcol * 4] = v;
    }
}

// ---------------------------------------------------------------------------
// Row softmax over 256 entries: one block (256 threads) per row, in-place.
// ---------------------------------------------------------------------------
__global__ void softmax256(float* __restrict__ S)
{
    __shared__ float red[256];
    const size_t row = blockIdx.x;
    const int t = threadIdx.x;
    float v = S[row * 256 + t];

    red[t] = v;
    __syncthreads();
    #pragma unroll
    for (int s = 128; s > 0; s >>= 1) {
        if (t < s) red[t] = fmaxf(red[t], red[t + s]);
        __syncthreads();
    }
    const float m = red[0];
    __syncthreads();

    const float e = expf(v - m);
    red[t] = e;
    __syncthreads();
    #pragma unroll
    for (int s = 128; s > 0; s >>= 1) {
        if (t < s) red[t] += red[t + s];
        __syncthreads();
    }
    S[row * 256 + t] = e / red[0];
}

// ---------------------------------------------------------------------------
// Launch
// ---------------------------------------------------------------------------
extern "C" void kernel_launch(void* const* d_in, const int* in_sizes, int n_in,
                              void* d_out, int out_size)
{
    const float* x = (const float*)d_in[0];   // [32,256,56,56]
    const float* W = (const float*)d_in[1];   // [256,256]
    const float* b = (const float*)d_in[2];   // [256]
    float* out = (float*)d_out;               // [32,256,56,56]

    // Resolve device-global scratch addresses once (first call is the
    // uncaptured correctness run; captured calls reuse the cached pointers).
    static float *qp = nullptr, *sp = nullptr, *op = nullptr;
    if (!qp) {
        cudaGetSymbolAddress((void**)&qp, g_q);
        cudaGetSymbolAddress((void**)&sp, g_s);
        cudaGetSymbolAddress((void**)&op, g_o);
    }

    const int C = CH, N = NPIX;
    const size_t sBN = (size_t)C * N;   // per-batch stride of [C,N] tensors
    const size_t sCC = (size_t)C * C;

    dim3 gBig(N / 64, C / 64, BATCH);   // (49, 4, 32)
    dim3 gGram(C / 64, C / 64, BATCH);  // (4, 4, 32)

    // Stage 1: q = W @ x + b          (A shared across batch: stride 0)
    gemm_nn<<<gBig, 256>>>(W, 0, x, sBN, qp, sBN, b, C, N, C);
    // Stage 2: S = q @ q^T            (K = NPIX, contiguous)
    gemm_nt<<<gGram, 256>>>(qp, sBN, qp, sBN, sp, sCC, C, C, N);
    // Stage 3: softmax rows of S (in place)
    softmax256<<<BATCH * C, 256>>>(sp);
    // Stage 4: o = attn @ q
    gemm_nn<<<gBig, 256>>>(sp, sCC, qp, sBN, op, sBN, nullptr, C, N, C);
    // Stage 5: out = W @ o + b
    gemm_nn<<<gBig, 256>>>(W, 0, op, sBN, out, sBN, b, C, N, C);
}

// round 2
// speedup vs baseline: 1.1916x; 1.1916x over previous
#include <cuda_runtime.h>
#include <cuda_bf16.h>

#define BATCH 32
#define CH    256
#define NPIX  3136          // 56*56

// Device-global scratch (no allocation allowed in kernel_launch)
__device__ float g_q[(size_t)BATCH * CH * NPIX];   // conv1 output
__device__ float g_s[(size_t)BATCH * CH * CH];     // scores / attn
__device__ float g_o[(size_t)BATCH * CH * NPIX];   // attn @ q

// ---------------------------------------------------------------------------
// Helpers: tf32 split + mma
// ---------------------------------------------------------------------------
__device__ __forceinline__ void tf32_split(float v, unsigned &h, unsigned &l)
{
    asm("cvt.rna.tf32.f32 %0, %1;" : "=r"(h) : "f"(v));
    float hf = __uint_as_float(h);
    asm("cvt.rna.tf32.f32 %0, %1;" : "=r"(l) : "f"(v - hf));
}

__device__ __forceinline__ void mma8(float* c, const unsigned* a, const unsigned* b)
{
    asm volatile(
        "mma.sync.aligned.m16n8k8.row.col.f32.tf32.tf32.f32 "
        "{%0,%1,%2,%3}, {%4,%5,%6,%7}, {%8,%9}, {%0,%1,%2,%3};"
        : "+f"(c[0]), "+f"(c[1]), "+f"(c[2]), "+f"(c[3])
        : "r"(a[0]), "r"(a[1]), "r"(a[2]), "r"(a[3]),
          "r"(b[0]), "r"(b[1]));
}

// ---------------------------------------------------------------------------
// 3xTF32 GEMM.
//   NT=false: C[b](MxN) = A[b](MxK) * B[b](KxN)   (+bias[m])
//   NT=true : C[b](MxN) = A[b](MxK) * B[b](NxK)^T (+bias[m])
// BM=128, BN=64, BK=16, 256 threads (8 warps: 4 along M x 2 along N,
// 32x32 per warp). Requires M%128==0, N%64==0, K%16==0.
// ---------------------------------------------------------------------------
template<bool NT>
__global__ void gemm3tf32(const float* __restrict__ A, size_t sA,
                          const float* __restrict__ B, size_t sB,
                          float* __restrict__ C, size_t sC,
                          const float* __restrict__ bias,
                          int M, int N, int K)
{
    constexpr int BM = 128, BN = 64, BK = 16;
    constexpr int ASTR = 136;   // 128 + 8 pad -> conflict-free frag loads
    constexpr int BSTR = 72;    // 64 + 8 pad

    __shared__ unsigned sAh[BK * ASTR], sAl[BK * ASTR];
    __shared__ unsigned sBh[BK * BSTR], sBl[BK * BSTR];

    const int bz = blockIdx.z;
    A += (size_t)bz * sA;
    B += (size_t)bz * sB;
    C += (size_t)bz * sC;

    const int m0 = blockIdx.y * BM;
    const int n0 = blockIdx.x * BN;
    const int tid  = threadIdx.x;
    const int lane = tid & 31;
    const int wid  = tid >> 5;
    const int wm   = wid & 3;        // warp row (x32)
    const int wn   = wid >> 2;       // warp col (x32)
    const int lq   = lane & 3;
    const int lr   = lane >> 2;

    float acc[2][4][4] = {};

    for (int k0 = 0; k0 < K; k0 += BK) {
        // --- stage A tile (BMxBK) as [k][m], split hi/lo ---
        {
            const int cg = (tid & 3) * 4;
            #pragma unroll
            for (int it = 0; it < 2; it++) {
                const int m = it * 64 + (tid >> 2);
                float4 av = *(const float4*)&A[(size_t)(m0 + m) * K + k0 + cg];
                float vv[4] = {av.x, av.y, av.z, av.w};
                #pragma unroll
                for (int j = 0; j < 4; j++) {
                    unsigned h, l;
                    tf32_split(vv[j], h, l);
                    sAh[(cg + j) * ASTR + m] = h;
                    sAl[(cg + j) * ASTR + m] = l;
                }
            }
        }
        // --- stage B tile (BKxBN) as [k][n], split hi/lo ---
        if (NT) {
            const int r  = tid >> 2;         // n index 0..63
            const int cg = (tid & 3) * 4;    // k group
            float4 bv = *(const float4*)&B[(size_t)(n0 + r) * K + k0 + cg];
            float vv[4] = {bv.x, bv.y, bv.z, bv.w};
            #pragma unroll
            for (int j = 0; j < 4; j++) {
                unsigned h, l;
                tf32_split(vv[j], h, l);
                sBh[(cg + j) * BSTR + r] = h;
                sBl[(cg + j) * BSTR + r] = l;
            }
        } else {
            const int r  = tid >> 4;         // k index 0..15
            const int cg = (tid & 15) * 4;   // n group
            float4 bv = *(const float4*)&B[(size_t)(k0 + r) * N + n0 + cg];
            float vv[4] = {bv.x, bv.y, bv.z, bv.w};
            #pragma unroll
            for (int j = 0; j < 4; j++) {
                unsigned h, l;
                tf32_split(vv[j], h, l);
                sBh[r * BSTR + cg + j] = h;
                sBl[r * BSTR + cg + j] = l;
            }
        }
        __syncthreads();

        #pragma unroll
        for (int ks = 0; ks < BK; ks += 8) {
            unsigned ah[2][4], al[2][4], bh[4][2], bl[4][2];
            #pragma unroll
            for (int mf = 0; mf < 2; mf++) {
                const int base = wm * 32 + mf * 16 + lr;
                const int kk = (ks + lq) * ASTR;
                const int kk4 = (ks + 4 + lq) * ASTR;
                ah[mf][0] = sAh[kk + base];      ah[mf][1] = sAh[kk + base + 8];
                ah[mf][2] = sAh[kk4 + base];     ah[mf][3] = sAh[kk4 + base + 8];
                al[mf][0] = sAl[kk + base];      al[mf][1] = sAl[kk + base + 8];
                al[mf][2] = sAl[kk4 + base];     al[mf][3] = sAl[kk4 + base + 8];
            }
            #pragma unroll
            for (int nf = 0; nf < 4; nf++) {
                const int col = wn * 32 + nf * 8 + lr;
                bh[nf][0] = sBh[(ks + lq) * BSTR + col];
                bh[nf][1] = sBh[(ks + 4 + lq) * BSTR + col];
                bl[nf][0] = sBl[(ks + lq) * BSTR + col];
                bl[nf][1] = sBl[(ks + 4 + lq) * BSTR + col];
            }
            #pragma unroll
            for (int mf = 0; mf < 2; mf++)
                #pragma unroll
                for (int nf = 0; nf < 4; nf++) {
                    mma8(acc[mf][nf], al[mf], bh[nf]);   // lo*hi
                    mma8(acc[mf][nf], ah[mf], bl[nf]);   // hi*lo
                    mma8(acc[mf][nf], ah[mf], bh[nf]);   // hi*hi
                }
        }
        __syncthreads();
    }

    // --- epilogue ---
    #pragma unroll
    for (int mf = 0; mf < 2; mf++) {
        const int m_r = m0 + wm * 32 + mf * 16 + lr;
        const float bb0 = bias ? bias[m_r] : 0.0f;
        const float bb1 = bias ? bias[m_r + 8] : 0.0f;
        #pragma unroll
        for (int nf = 0; nf < 4; nf++) {
            const int n_c = n0 + wn * 32 + nf * 8 + 2 * lq;
            float2 v0 = make_float2(acc[mf][nf][0] + bb0, acc[mf][nf][1] + bb0);
            float2 v1 = make_float2(acc[mf][nf][2] + bb1, acc[mf][nf][3] + bb1);
            *(float2*)&C[(size_t)m_r * N + n_c]       = v0;
            *(float2*)&C[(size_t)(m_r + 8) * N + n_c] = v1;
        }
    }
}

// ---------------------------------------------------------------------------
// Row softmax over 256 entries: one block (256 threads) per row, in-place.
// ---------------------------------------------------------------------------
__global__ void softmax256(float* __restrict__ S)
{
    __shared__ float red[256];
    const size_t row = blockIdx.x;
    const int t = threadIdx.x;
    float v = S[row * 256 + t];

    red[t] = v;
    __syncthreads();
    #pragma unroll
    for (int s = 128; s > 0; s >>= 1) {
        if (t < s) red[t] = fmaxf(red[t], red[t + s]);
        __syncthreads();
    }
    const float m = red[0];
    __syncthreads();

    const float e = expf(v - m);
    red[t] = e;
    __syncthreads();
    #pragma unroll
    for (int s = 128; s > 0; s >>= 1) {
        if (t < s) red[t] += red[t + s];
        __syncthreads();
    }
    S[row * 256 + t] = e / red[0];
}

// ---------------------------------------------------------------------------
// Launch
// ---------------------------------------------------------------------------
extern "C" void kernel_launch(void* const* d_in, const int* in_sizes, int n_in,
                              void* d_out, int out_size)
{
    const float* x = (const float*)d_in[0];   // [32,256,56,56]
    const float* W = (const float*)d_in[1];   // [256,256]
    const float* b = (const float*)d_in[2];   // [256]
    float* out = (float*)d_out;

    static float *qp = nullptr, *sp = nullptr, *op = nullptr;
    if (!qp) {
        cudaGetSymbolAddress((void**)&qp, g_q);
        cudaGetSymbolAddress((void**)&sp, g_s);
        cudaGetSymbolAddress((void**)&op, g_o);
    }

    const int C = CH, N = NPIX;
    const size_t sBN = (size_t)C * N;
    const size_t sCC = (size_t)C * C;

    dim3 gConv(N / 64, C / 128, BATCH);   // (49, 2, 32)
    dim3 gGram(C / 64, C / 128, BATCH);   // (4, 2, 32)

    // Stage 1: q = W @ x + b              (A shared across batch: stride 0)
    gemm3tf32<false><<<gConv, 256>>>(W, 0, x, sBN, qp, sBN, b, C, N, C);
    // Stage 2: S = q @ q^T                (NT, K = NPIX)
    gemm3tf32<true><<<gGram, 256>>>(qp, sBN, qp, sBN, sp, sCC, nullptr, C, C, N);
    // Stage 3: softmax rows of S (in place)
    softmax256<<<BATCH * C, 256>>>(sp);
    // Stage 4: o = attn @ q
    gemm3tf32<false><<<gConv, 256>>>(sp, sCC, qp, sBN, op, sBN, nullptr, C, N, C);
    // Stage 5: out = W @ o + b
    gemm3tf32<false><<<gConv, 256>>>(W, 0, op, sBN, out, sBN, b, C, N, C);
}